// round 6
// baseline (speedup 1.0000x reference)
#include <cuda_runtime.h>

#define BN 24
#define BM 128
#define BK 64
#define NITER 8
#define NFIX 12
#define NACT 12
#define PIF 3.14159274101257324f   // float32(np.pi)
#define BLOCK 224
#define GPB (BLOCK / 16)           // 14 batches (16-lane groups) per block

typedef unsigned long long u64;

// ---------------------------------------------------------------------------
// packed f32x2 helpers (sm_100+): one instr operates on 2 floats in a b64 reg
// ---------------------------------------------------------------------------
__device__ __forceinline__ u64 pack2(float x, float y) {
    u64 r; asm("mov.b64 %0, {%1,%2};" : "=l"(r) : "f"(x), "f"(y)); return r;
}
__device__ __forceinline__ void unpack2(u64 v, float& x, float& y) {
    asm("mov.b64 {%0,%1}, %2;" : "=f"(x), "=f"(y) : "l"(v));
}
__device__ __forceinline__ u64 fma2p(u64 a, u64 b, u64 c) {   // a*b + c
    u64 d; asm("fma.rn.f32x2 %0, %1, %2, %3;" : "=l"(d) : "l"(a), "l"(b), "l"(c)); return d;
}
__device__ __forceinline__ u64 mul2p(u64 a, u64 b) {
    u64 d; asm("mul.rn.f32x2 %0, %1, %2;" : "=l"(d) : "l"(a), "l"(b)); return d;
}
__device__ __forceinline__ u64 add2p(u64 a, u64 b) {
    u64 d; asm("add.rn.f32x2 %0, %1, %2;" : "=l"(d) : "l"(a), "l"(b)); return d;
}

// ---------------------------------------------------------------------------
__device__ __forceinline__ float dot4(float4 a, float4 b) {
    return fmaf(a.x, b.x, fmaf(a.y, b.y, fmaf(a.z, b.z, a.w * b.w)));
}
__device__ __forceinline__ float4 mul4(float4 a, float s) {
    return make_float4(a.x * s, a.y * s, a.z * s, a.w * s);
}
__device__ __forceinline__ float4 fma4(float4 a, float s, float4 c) {
    return make_float4(fmaf(a.x, s, c.x), fmaf(a.y, s, c.y),
                       fmaf(a.z, s, c.z), fmaf(a.w, s, c.w));
}
__device__ __forceinline__ float gsum16(float v) {
    v += __shfl_xor_sync(0xffffffffu, v, 8);
    v += __shfl_xor_sync(0xffffffffu, v, 4);
    v += __shfl_xor_sync(0xffffffffu, v, 2);
    v += __shfl_xor_sync(0xffffffffu, v, 1);
    return v;
}
__device__ __forceinline__ void gsum16_2(float& a, float& b) {
    a += __shfl_xor_sync(0xffffffffu, a, 8); b += __shfl_xor_sync(0xffffffffu, b, 8);
    a += __shfl_xor_sync(0xffffffffu, a, 4); b += __shfl_xor_sync(0xffffffffu, b, 4);
    a += __shfl_xor_sync(0xffffffffu, a, 2); b += __shfl_xor_sync(0xffffffffu, b, 2);
    a += __shfl_xor_sync(0xffffffffu, a, 1); b += __shfl_xor_sync(0xffffffffu, b, 1);
}
__device__ __forceinline__ float wsum32(float v) {
    v += __shfl_xor_sync(0xffffffffu, v, 16);
    return gsum16(v);
}
__device__ __forceinline__ float out_angle(float co) {
    float c = fminf(fmaxf(-co, -1.0f + 1e-6f), 1.0f - 1e-6f);
    return acosf(c) / PIF;
}

// ---------------------------------------------------------------------------
// One 16-lane group per batch element; lane owns comps 4*gl .. 4*gl+3,
// held as two f32x2-packed b64 registers.
// ---------------------------------------------------------------------------
__global__ void __launch_bounds__(BLOCK) mix_kernel(
    const float* __restrict__ z,
    const float* __restrict__ S,
    const float* __restrict__ Vr,
    const int* __restrict__ isin,
    float* __restrict__ out,
    int B)
{
    // Gram rows 12..23: scalar (all 24 cols) + duplicated-pair active block
    __shared__ __align__(16) float  Gs2[NACT * BN];
    __shared__ __align__(16) float2 Gdup[NACT * NACT];   // {w,w} per entry

    const int tid  = threadIdx.x;
    const int wlid = tid & 31;
    const int wid  = tid >> 5;             // 7 warps

    // ---- phase 0: 288 Gram entries, warp-cooperative (lanes span M=128) ----
    const float4* S4 = (const float4*)S;   // S4[i*32 + m4]
    for (int e = wid; e < NACT * BN; e += BLOCK / 32) {
        int i = NFIX + e / BN, j = e % BN;
        float part = dot4(S4[i * 32 + wlid], S4[j * 32 + wlid]);
        float g = wsum32(part);
        if (wlid == 0) {
            Gs2[e] = g;
            if (j >= NFIX)
                Gdup[(i - NFIX) * NACT + (j - NFIX)] = make_float2(g, g);
        }
    }
    __syncthreads();

    const int grp = tid >> 4;
    const int gl  = tid & 15;
    int b = blockIdx.x * GPB + grp;
    if (b >= B) b = B - 1;    // duplicate work, deterministic

    const float4* vrow = (const float4*)Vr + (size_t)b * BN * (BK / 4);
    float*        outb = out + (size_t)b * BN;

    unsigned mask = 0;
#pragma unroll
    for (int n = 0; n < BN; n++)
        mask |= (isin[b * BN + n] > 0) ? (1u << n) : 0u;

    // ---- v0 ----
    float4 f0  = vrow[gl];
    float  ss0 = gsum16(dot4(f0, f0));
    float4 v0  = mul4(f0, rsqrtf(fmaxf(ss0, 1e-30f)));

    if (mask == 0xFFFu) {
        // ================= FAST PATH: inputs are rows 0..11 =================
        float nv0 = gsum16(dot4(v0, v0));      // |v0|^2 (~1), row-0 output
        if (gl == 0) outb[0] = out_angle(nv0);

        const u64 v001 = pack2(v0.x, v0.y);
        const u64 v023 = pack2(v0.z, v0.w);

        u64 h01[NACT], h23[NACT];
#pragma unroll
        for (int ii = 0; ii < NACT; ii++) {
            float w = Gs2[ii * BN + 0];
            u64 wp = pack2(w, w);
            h01[ii] = mul2p(v001, wp);
            h23[ii] = mul2p(v023, wp);
        }

        // fixed input rows 1..11
#pragma unroll
        for (int n = 1; n < NFIX; n++) {
            float4 f  = vrow[n * 16 + gl];
            float  ss = dot4(f, f);
            float  fv = dot4(f, v0);
            gsum16_2(ss, fv);
            float ww = fmaf(-fv * fv, 2.0f - nv0, ss);   // |f - fv*v0|^2
            float iu = rsqrtf(fmaxf(ww, 1e-24f));
            float4 u = mul4(fma4(v0, -fv, f), iu);
            float sz, cz;
            __sincosf(PIF * z[b * BN + n], &sz, &cz);
            float4 vv = fma4(v0, -cz, mul4(u, sz));
            // vv.v0 = -cz*|v0|^2 + sz*iu*fv*(1-|v0|^2): broadcast scalars only
            float co = fmaf(-cz, nv0, sz * iu * fv * (1.0f - nv0));
            if (gl == 0) outb[n] = out_angle(co);
            u64 vv01 = pack2(vv.x, vv.y);
            u64 vv23 = pack2(vv.z, vv.w);
#pragma unroll
            for (int ii = 0; ii < NACT; ii++) {
                float w = Gs2[ii * BN + n];
                u64 wp = pack2(w, w);
                h01[ii] = fma2p(vv01, wp, h01[ii]);
                h23[ii] = fma2p(vv23, wp, h23[ii]);
            }
        }

        // free rows 12..23 (paired reductions), stored packed
        u64 A01[NACT], A23[NACT];
#pragma unroll
        for (int jj = 0; jj < NACT; jj += 2) {
            float4 fa = vrow[(NFIX + jj) * 16 + gl];
            float4 fb = vrow[(NFIX + jj + 1) * 16 + gl];
            float  sa = dot4(fa, fa);
            float  sb = dot4(fb, fb);
            gsum16_2(sa, sb);
            float4 na = mul4(fa, rsqrtf(fmaxf(sa, 1e-30f)));
            float4 nb = mul4(fb, rsqrtf(fmaxf(sb, 1e-30f)));
            A01[jj]     = pack2(na.x, na.y);  A23[jj]     = pack2(na.z, na.w);
            A01[jj + 1] = pack2(nb.x, nb.y);  A23[jj + 1] = pack2(nb.z, nb.w);
        }

        // ---- software-pipelined Gauss–Seidel, packed f32x2 ----
        // Invariant at loop head: p = h[ii] + sum_{jj!=ii} G[ii][jj]*A[jj]
        u64 p01, p23;
        {
            const ulonglong2* gr = (const ulonglong2*)&Gdup[0];
            ulonglong2 g0 = gr[0], g1 = gr[1], g2 = gr[2],
                       g3 = gr[3], g4 = gr[4], g5 = gr[5];
            const u64 wp[NACT] = { g0.x, g0.y, g1.x, g1.y, g2.x, g2.y,
                                   g3.x, g3.y, g4.x, g4.y, g5.x, g5.y };
            p01 = h01[0]; p23 = h23[0];
#pragma unroll
            for (int jj = 1; jj < NACT; jj++) {
                p01 = fma2p(A01[jj], wp[jj], p01);
                p23 = fma2p(A23[jj], wp[jj], p23);
            }
        }

        for (int t = 0; t < NITER; t++) {
#pragma unroll
            for (int ii = 0; ii < NACT; ii++) {
                // launch this step's reduction first...
                u64 sq = fma2p(p23, p23, mul2p(p01, p01));
                float sa, sb; unpack2(sq, sa, sb);
                float s = gsum16(sa + sb);

                // ...hide its latency building the next step's partial sum
                const int nx = (ii + 1) % NACT;
                const ulonglong2* gr = (const ulonglong2*)&Gdup[nx * NACT];
                ulonglong2 g0 = gr[0], g1 = gr[1], g2 = gr[2],
                           g3 = gr[3], g4 = gr[4], g5 = gr[5];
                const u64 wp[NACT] = { g0.x, g0.y, g1.x, g1.y, g2.x, g2.y,
                                       g3.x, g3.y, g4.x, g4.y, g5.x, g5.y };
                u64 qa01 = h01[nx], qb01 = 0ull;
                u64 qa23 = h23[nx], qb23 = 0ull;
#pragma unroll
                for (int jj = 0; jj < NACT; jj++) {
                    if (jj == nx || jj == ii) continue;
                    if (jj & 1) { qb01 = fma2p(A01[jj], wp[jj], qb01);
                                  qb23 = fma2p(A23[jj], wp[jj], qb23); }
                    else        { qa01 = fma2p(A01[jj], wp[jj], qa01);
                                  qa23 = fma2p(A23[jj], wp[jj], qa23); }
                }

                float inv = rsqrtf(fmaxf(s, 1e-30f));
                u64 ni = pack2(-inv, -inv);
                u64 An01 = mul2p(p01, ni);
                u64 An23 = mul2p(p23, ni);
                A01[ii] = An01; A23[ii] = An23;
                p01 = fma2p(An01, wp[ii], add2p(qa01, qb01));
                p23 = fma2p(An23, wp[ii], add2p(qa23, qb23));
            }
        }

        // active outputs (paired reductions)
#pragma unroll
        for (int ii = 0; ii < NACT; ii += 2) {
            float a0, a1, a2, a3, b0, b1, b2, b3;
            unpack2(A01[ii], a0, a1);     unpack2(A23[ii], a2, a3);
            unpack2(A01[ii + 1], b0, b1); unpack2(A23[ii + 1], b2, b3);
            float c0 = fmaf(a0, v0.x, fmaf(a1, v0.y, fmaf(a2, v0.z, a3 * v0.w)));
            float c1 = fmaf(b0, v0.x, fmaf(b1, v0.y, fmaf(b2, v0.z, b3 * v0.w)));
            gsum16_2(c0, c1);
            if (gl == 0) {
                outb[NFIX + ii]     = out_angle(c0);
                outb[NFIX + ii + 1] = out_angle(c1);
            }
        }
    } else {
        // ============ GENERIC PATH (any mask) — cold =========================
        float Gc[BN * BN];
#pragma unroll 1
        for (int e = 0; e < BN * BN; e++) {
            int i = e / BN, j = e % BN;
            float part = dot4(S4[i * 32 + gl],      S4[j * 32 + gl]) +
                         dot4(S4[i * 32 + 16 + gl], S4[j * 32 + 16 + gl]);
            Gc[e] = gsum16(part);
        }

        float4 Vl[BN];
        Vl[0] = v0;
        float nv0g = gsum16(dot4(v0, v0));
#pragma unroll 1
        for (int n = 1; n < BN; n++) {
            float4 f  = vrow[n * 16 + gl];
            float  ss = dot4(f, f);
            float  fv = dot4(f, v0);
            gsum16_2(ss, fv);
            float4 r = mul4(f, rsqrtf(fmaxf(ss, 1e-30f)));
            if ((mask >> n) & 1u) {
                float ww = fmaf(-fv * fv, 2.0f - nv0g, ss);
                float iu = rsqrtf(fmaxf(ww, 1e-24f));
                float4 u = mul4(fma4(v0, -fv, f), iu);
                float sz, cz;
                __sincosf(PIF * z[b * BN + n], &sz, &cz);
                Vl[n] = fma4(v0, -cz, mul4(u, sz));
            } else {
                Vl[n] = r;
            }
        }
#pragma unroll 1
        for (int t = 0; t < NITER; t++) {
#pragma unroll 1
            for (int i = 0; i < BN; i++) {
                if ((mask >> i) & 1u) continue;
                float4 acc = make_float4(0.f, 0.f, 0.f, 0.f);
#pragma unroll 1
                for (int n = 0; n < BN; n++)
                    acc = fma4(Vl[n], Gc[i * BN + n], acc);
                acc = fma4(Vl[i], -Gc[i * BN + i], acc);
                float s = gsum16(dot4(acc, acc));
                Vl[i] = mul4(acc, -rsqrtf(fmaxf(s, 1e-30f)));
            }
        }
#pragma unroll 1
        for (int n = 0; n < BN; n++) {
            float co = gsum16(dot4(Vl[n], v0));
            if (gl == 0) outb[n] = out_angle(co);
        }
    }
}

// ---------------------------------------------------------------------------
extern "C" void kernel_launch(void* const* d_in, const int* in_sizes, int n_in,
                              void* d_out, int out_size) {
    const float* z    = (const float*)d_in[0];   // (B, 24)
    const float* S    = (const float*)d_in[1];   // (24, 128)
    const float* Vr   = (const float*)d_in[2];   // (B, 24, 64)
    const int*   isin = (const int*)d_in[3];     // (B, 24)
    float*       out  = (float*)d_out;           // (B, 24)

    const int B = in_sizes[0] / BN;
    const int grid = (B + GPB - 1) / GPB;
    mix_kernel<<<grid, BLOCK>>>(z, S, Vr, isin, out, B);
}

// round 8
// speedup vs baseline: 8.5667x; 8.5667x over previous
#include <cuda_runtime.h>

#define BN 24
#define BM 128
#define BK 64
#define NITER 8
#define NFIX 12
#define NACT 12
#define PIF 3.14159274101257324f   // float32(np.pi)
#define BLOCK 224
#define GPB (BLOCK / 16)           // 14 batches (16-lane groups) per block

// ---------------------------------------------------------------------------
__device__ __forceinline__ float dot4(float4 a, float4 b) {
    return fmaf(a.x, b.x, fmaf(a.y, b.y, fmaf(a.z, b.z, a.w * b.w)));
}
__device__ __forceinline__ float4 mul4(float4 a, float s) {
    return make_float4(a.x * s, a.y * s, a.z * s, a.w * s);
}
__device__ __forceinline__ float4 fma4(float4 a, float s, float4 c) {
    return make_float4(fmaf(a.x, s, c.x), fmaf(a.y, s, c.y),
                       fmaf(a.z, s, c.z), fmaf(a.w, s, c.w));
}
// sum over 16-lane subgroup (xor 8,4,2,1 stays in group)
__device__ __forceinline__ float gsum16(float v) {
    v += __shfl_xor_sync(0xffffffffu, v, 8);
    v += __shfl_xor_sync(0xffffffffu, v, 4);
    v += __shfl_xor_sync(0xffffffffu, v, 2);
    v += __shfl_xor_sync(0xffffffffu, v, 1);
    return v;
}
__device__ __forceinline__ void gsum16_2(float& a, float& b) {
    a += __shfl_xor_sync(0xffffffffu, a, 8); b += __shfl_xor_sync(0xffffffffu, b, 8);
    a += __shfl_xor_sync(0xffffffffu, a, 4); b += __shfl_xor_sync(0xffffffffu, b, 4);
    a += __shfl_xor_sync(0xffffffffu, a, 2); b += __shfl_xor_sync(0xffffffffu, b, 2);
    a += __shfl_xor_sync(0xffffffffu, a, 1); b += __shfl_xor_sync(0xffffffffu, b, 1);
}
// full-warp sum (for the Gram prologue)
__device__ __forceinline__ float wsum32(float v) {
    v += __shfl_xor_sync(0xffffffffu, v, 16);
    return gsum16(v);
}
__device__ __forceinline__ float out_angle(float co) {
    float c = fminf(fmaxf(-co, -1.0f + 1e-6f), 1.0f - 1e-6f);
    return acosf(c) / PIF;
}

// ---------------------------------------------------------------------------
// One 16-lane group per batch element; lane owns comps 4*gl .. 4*gl+3.
// ---------------------------------------------------------------------------
__global__ void __launch_bounds__(BLOCK) mix_kernel(
    const float* __restrict__ z,
    const float* __restrict__ S,
    const float* __restrict__ Vr,
    const int* __restrict__ isin,
    float* __restrict__ out,
    int B)
{
    // Only Gram rows 12..23 are needed in the hot path:
    // Gs2[r*BN + c] = G[12+r][c]
    __shared__ __align__(16) float Gs2[NACT * BN];

    const int tid  = threadIdx.x;
    const int wlid = tid & 31;            // lane within warp
    const int wid  = tid >> 5;            // warp id (7 warps)

    // ---- phase 0: 288 Gram entries, warp-cooperative (lanes span M=128) ----
    const float4* S4 = (const float4*)S;  // S4[i*32 + m4]
    for (int e = wid; e < NACT * BN; e += BLOCK / 32) {
        int i = NFIX + e / BN, j = e % BN;
        float part = dot4(S4[i * 32 + wlid], S4[j * 32 + wlid]);
        float g = wsum32(part);
        if (wlid == 0) Gs2[e] = g;
    }
    __syncthreads();

    const int grp = tid >> 4;
    const int gl  = tid & 15;
    int b = blockIdx.x * GPB + grp;
    if (b >= B) b = B - 1;    // duplicate work, deterministic

    const float4* vrow = (const float4*)Vr + (size_t)b * BN * (BK / 4);
    float*        outb = out + (size_t)b * BN;

    unsigned mask = 0;
#pragma unroll
    for (int n = 0; n < BN; n++)
        mask |= (isin[b * BN + n] > 0) ? (1u << n) : 0u;

    // ---- v0 ----
    float4 f0  = vrow[gl];
    float  ss0 = gsum16(dot4(f0, f0));
    float4 v0  = mul4(f0, rsqrtf(fmaxf(ss0, 1e-30f)));

    if (mask == 0xFFFu) {
        // ================= FAST PATH: inputs are rows 0..11 =================
        float nv0 = gsum16(dot4(v0, v0));      // |v0|^2 (~1), row-0 output
        if (gl == 0) outb[0] = out_angle(nv0);

        float4 h[NACT];
#pragma unroll
        for (int ii = 0; ii < NACT; ii++)
            h[ii] = mul4(v0, Gs2[ii * BN + 0]);

        // fixed input rows 1..11 (independent -> ILP; one paired reduction each)
#pragma unroll
        for (int n = 1; n < NFIX; n++) {
            float4 f  = vrow[n * 16 + gl];
            float  ss = dot4(f, f);
            float  fv = dot4(f, v0);
            gsum16_2(ss, fv);
            float ww = fmaf(-fv * fv, 2.0f - nv0, ss);   // |f - fv*v0|^2
            float iu = rsqrtf(fmaxf(ww, 1e-24f));
            float4 u = mul4(fma4(v0, -fv, f), iu);
            float sz, cz;
            __sincosf(PIF * z[b * BN + n], &sz, &cz);
            float4 vv = fma4(v0, -cz, mul4(u, sz));
            // vv.v0 = -cz*|v0|^2 + sz*iu*fv*(1-|v0|^2): broadcast scalars only
            float co = fmaf(-cz, nv0, sz * iu * fv * (1.0f - nv0));
            if (gl == 0) outb[n] = out_angle(co);
#pragma unroll
            for (int ii = 0; ii < NACT; ii++)
                h[ii] = fma4(vv, Gs2[ii * BN + n], h[ii]);
        }

        // free rows 12..23 (paired reductions)
        float4 A[NACT];
#pragma unroll
        for (int jj = 0; jj < NACT; jj += 2) {
            float4 fa = vrow[(NFIX + jj) * 16 + gl];
            float4 fb = vrow[(NFIX + jj + 1) * 16 + gl];
            float  sa = dot4(fa, fa);
            float  sb = dot4(fb, fb);
            gsum16_2(sa, sb);
            A[jj]     = mul4(fa, rsqrtf(fmaxf(sa, 1e-30f)));
            A[jj + 1] = mul4(fb, rsqrtf(fmaxf(sb, 1e-30f)));
        }

        // ---- software-pipelined Gauss–Seidel: 8 sweeps x 12 steps ----
        // Invariant at loop head: p = h[ii] + sum_{jj!=ii} G[ii][jj]*A[jj]
        // with correct GS recency.
        float4 p;
        {
            const float4* gr = (const float4*)&Gs2[0 * BN + NFIX];
            float4 w0 = gr[0], w1 = gr[1], w2 = gr[2];
            const float wv[NACT] = { w0.x, w0.y, w0.z, w0.w,
                                     w1.x, w1.y, w1.z, w1.w,
                                     w2.x, w2.y, w2.z, w2.w };
            p = h[0];
#pragma unroll
            for (int jj = 1; jj < NACT; jj++) p = fma4(A[jj], wv[jj], p);
        }

        for (int t = 0; t < NITER; t++) {
#pragma unroll
            for (int ii = 0; ii < NACT; ii++) {
                // launch this step's reduction first...
                float s = gsum16(dot4(p, p));

                // ...hide its latency building the next step's partial sum
                const int nx = (ii + 1) % NACT;
                const float4* gr = (const float4*)&Gs2[nx * BN + NFIX];
                float4 w0 = gr[0], w1 = gr[1], w2 = gr[2];
                const float wv[NACT] = { w0.x, w0.y, w0.z, w0.w,
                                         w1.x, w1.y, w1.z, w1.w,
                                         w2.x, w2.y, w2.z, w2.w };
                float4 q0 = h[nx];
                float4 q1 = make_float4(0.f, 0.f, 0.f, 0.f);
#pragma unroll
                for (int jj = 0; jj < NACT; jj++) {
                    if (jj == nx || jj == ii) continue;
                    if (jj & 1) q1 = fma4(A[jj], wv[jj], q1);
                    else        q0 = fma4(A[jj], wv[jj], q0);
                }

                float  inv = -rsqrtf(fmaxf(s, 1e-30f));
                float4 An  = mul4(p, inv);
                A[ii] = An;
                p = fma4(An, wv[ii],
                         make_float4(q0.x + q1.x, q0.y + q1.y,
                                     q0.z + q1.z, q0.w + q1.w));
            }
        }

        // active outputs (paired reductions)
#pragma unroll
        for (int ii = 0; ii < NACT; ii += 2) {
            float c0 = dot4(A[ii], v0);
            float c1 = dot4(A[ii + 1], v0);
            gsum16_2(c0, c1);
            if (gl == 0) {
                outb[NFIX + ii]     = out_angle(c0);
                outb[NFIX + ii + 1] = out_angle(c1);
            }
        }
    } else {
        // ============ GENERIC PATH (any mask) — cold =========================
        // Per-group full Gram into local memory (16 lanes x 2 float4 span M=128)
        float Gc[BN * BN];
#pragma unroll 1
        for (int e = 0; e < BN * BN; e++) {
            int i = e / BN, j = e % BN;
            float part = dot4(S4[i * 32 + gl],      S4[j * 32 + gl]) +
                         dot4(S4[i * 32 + 16 + gl], S4[j * 32 + 16 + gl]);
            Gc[e] = gsum16(part);
        }

        float4 Vl[BN];
        Vl[0] = v0;
        float nv0g = gsum16(dot4(v0, v0));
#pragma unroll 1
        for (int n = 1; n < BN; n++) {
            float4 f  = vrow[n * 16 + gl];
            float  ss = dot4(f, f);
            float  fv = dot4(f, v0);
            gsum16_2(ss, fv);
            float4 r = mul4(f, rsqrtf(fmaxf(ss, 1e-30f)));
            if ((mask >> n) & 1u) {
                float ww = fmaf(-fv * fv, 2.0f - nv0g, ss);
                float iu = rsqrtf(fmaxf(ww, 1e-24f));
                float4 u = mul4(fma4(v0, -fv, f), iu);
                float sz, cz;
                __sincosf(PIF * z[b * BN + n], &sz, &cz);
                Vl[n] = fma4(v0, -cz, mul4(u, sz));
            } else {
                Vl[n] = r;
            }
        }
#pragma unroll 1
        for (int t = 0; t < NITER; t++) {
#pragma unroll 1
            for (int i = 0; i < BN; i++) {
                if ((mask >> i) & 1u) continue;
                float4 acc = make_float4(0.f, 0.f, 0.f, 0.f);
#pragma unroll 1
                for (int n = 0; n < BN; n++)
                    acc = fma4(Vl[n], Gc[i * BN + n], acc);
                acc = fma4(Vl[i], -Gc[i * BN + i], acc);
                float s = gsum16(dot4(acc, acc));
                Vl[i] = mul4(acc, -rsqrtf(fmaxf(s, 1e-30f)));
            }
        }
#pragma unroll 1
        for (int n = 0; n < BN; n++) {
            float co = gsum16(dot4(Vl[n], v0));
            if (gl == 0) outb[n] = out_angle(co);
        }
    }
}

// ---------------------------------------------------------------------------
extern "C" void kernel_launch(void* const* d_in, const int* in_sizes, int n_in,
                              void* d_out, int out_size) {
    const float* z    = (const float*)d_in[0];   // (B, 24)
    const float* S    = (const float*)d_in[1];   // (24, 128)
    const float* Vr   = (const float*)d_in[2];   // (B, 24, 64)
    const int*   isin = (const int*)d_in[3];     // (B, 24)
    float*       out  = (float*)d_out;           // (B, 24)

    const int B = in_sizes[0] / BN;
    const int grid = (B + GPB - 1) / GPB;
    mix_kernel<<<grid, BLOCK>>>(z, S, Vr, isin, out, B);
}

// round 9
// speedup vs baseline: 9.7905x; 1.1429x over previous
#include <cuda_runtime.h>

#define BN 24
#define BM 128
#define BK 64
#define NITER 8
#define NFIX 12
#define NACT 12
#define PIF 3.14159274101257324f   // float32(np.pi)
#define BLOCK 256
#define GPB (BLOCK / 16)           // 16 batches (16-lane groups) per block

// ---------------------------------------------------------------------------
__device__ __forceinline__ float dot4(float4 a, float4 b) {
    return fmaf(a.x, b.x, fmaf(a.y, b.y, fmaf(a.z, b.z, a.w * b.w)));
}
__device__ __forceinline__ float4 mul4(float4 a, float s) {
    return make_float4(a.x * s, a.y * s, a.z * s, a.w * s);
}
__device__ __forceinline__ float4 fma4(float4 a, float s, float4 c) {
    return make_float4(fmaf(a.x, s, c.x), fmaf(a.y, s, c.y),
                       fmaf(a.z, s, c.z), fmaf(a.w, s, c.w));
}
// sum over 16-lane subgroup (xor 8,4,2,1 stays in group)
__device__ __forceinline__ float gsum16(float v) {
    v += __shfl_xor_sync(0xffffffffu, v, 8);
    v += __shfl_xor_sync(0xffffffffu, v, 4);
    v += __shfl_xor_sync(0xffffffffu, v, 2);
    v += __shfl_xor_sync(0xffffffffu, v, 1);
    return v;
}
__device__ __forceinline__ void gsum16_2(float& a, float& b) {
    a += __shfl_xor_sync(0xffffffffu, a, 8); b += __shfl_xor_sync(0xffffffffu, b, 8);
    a += __shfl_xor_sync(0xffffffffu, a, 4); b += __shfl_xor_sync(0xffffffffu, b, 4);
    a += __shfl_xor_sync(0xffffffffu, a, 2); b += __shfl_xor_sync(0xffffffffu, b, 2);
    a += __shfl_xor_sync(0xffffffffu, a, 1); b += __shfl_xor_sync(0xffffffffu, b, 1);
}
// full-warp sum (for the Gram prologue)
__device__ __forceinline__ float wsum32(float v) {
    v += __shfl_xor_sync(0xffffffffu, v, 16);
    return gsum16(v);
}
__device__ __forceinline__ float out_angle(float co) {
    float c = fminf(fmaxf(-co, -1.0f + 1e-6f), 1.0f - 1e-6f);
    return acosf(c) / PIF;
}

// ---------------------------------------------------------------------------
// One 16-lane group per batch element; lane owns comps 4*gl .. 4*gl+3.
// ---------------------------------------------------------------------------
__global__ void __launch_bounds__(BLOCK) mix_kernel(
    const float* __restrict__ z,
    const float* __restrict__ S,
    const float* __restrict__ Vr,
    const int* __restrict__ isin,
    float* __restrict__ out,
    int B)
{
    // Only Gram rows 12..23 are needed in the hot path:
    // Gs2[r*BN + c] = G[12+r][c]
    __shared__ __align__(16) float Gs2[NACT * BN];

    const int tid  = threadIdx.x;
    const int wlid = tid & 31;            // lane within warp
    const int wid  = tid >> 5;            // warp id (8 warps)

    // ---- phase 0: 288 Gram entries, warp-cooperative (lanes span M=128) ----
    const float4* S4 = (const float4*)S;  // S4[i*32 + m4]
#pragma unroll
    for (int e = wid; e < NACT * BN; e += BLOCK / 32) {
        int i = NFIX + e / BN, j = e % BN;
        float part = dot4(S4[i * 32 + wlid], S4[j * 32 + wlid]);
        float g = wsum32(part);
        if (wlid == 0) Gs2[e] = g;
    }
    __syncthreads();

    const int grp = tid >> 4;
    const int gl  = tid & 15;
    int b = blockIdx.x * GPB + grp;
    if (b >= B) b = B - 1;    // duplicate work, deterministic

    const float4* vrow = (const float4*)Vr + (size_t)b * BN * (BK / 4);
    float*        outb = out + (size_t)b * BN;

    unsigned mask = 0;
#pragma unroll
    for (int n = 0; n < BN; n++)
        mask |= (isin[b * BN + n] > 0) ? (1u << n) : 0u;

    // ---- v0 ----
    float4 f0  = vrow[gl];
    float  ss0 = gsum16(dot4(f0, f0));
    float4 v0  = mul4(f0, rsqrtf(fmaxf(ss0, 1e-30f)));

    if (mask == 0xFFFu) {
        // ================= FAST PATH: inputs are rows 0..11 =================
        float nv0 = gsum16(dot4(v0, v0));      // |v0|^2 (~1), row-0 output
        if (gl == 0) outb[0] = out_angle(nv0);

        float4 h[NACT];
#pragma unroll
        for (int ii = 0; ii < NACT; ii++)
            h[ii] = mul4(v0, Gs2[ii * BN + 0]);

        // fixed input rows 1..11 (independent -> ILP; one paired reduction each)
#pragma unroll
        for (int n = 1; n < NFIX; n++) {
            float4 f  = vrow[n * 16 + gl];
            float  ss = dot4(f, f);
            float  fv = dot4(f, v0);
            gsum16_2(ss, fv);
            float ww = fmaf(-fv * fv, 2.0f - nv0, ss);   // |f - fv*v0|^2
            float iu = rsqrtf(fmaxf(ww, 1e-24f));
            float4 u = mul4(fma4(v0, -fv, f), iu);
            float sz, cz;
            __sincosf(PIF * z[b * BN + n], &sz, &cz);
            float4 vv = fma4(v0, -cz, mul4(u, sz));
            // vv.v0 = -cz*|v0|^2 + sz*iu*fv*(1-|v0|^2): broadcast scalars only
            float co = fmaf(-cz, nv0, sz * iu * fv * (1.0f - nv0));
            if (gl == 0) outb[n] = out_angle(co);
#pragma unroll
            for (int ii = 0; ii < NACT; ii++)
                h[ii] = fma4(vv, Gs2[ii * BN + n], h[ii]);
        }

        // free rows 12..23 (paired reductions)
        float4 A[NACT];
#pragma unroll
        for (int jj = 0; jj < NACT; jj += 2) {
            float4 fa = vrow[(NFIX + jj) * 16 + gl];
            float4 fb = vrow[(NFIX + jj + 1) * 16 + gl];
            float  sa = dot4(fa, fa);
            float  sb = dot4(fb, fb);
            gsum16_2(sa, sb);
            A[jj]     = mul4(fa, rsqrtf(fmaxf(sa, 1e-30f)));
            A[jj + 1] = mul4(fb, rsqrtf(fmaxf(sb, 1e-30f)));
        }

        // ---- software-pipelined Gauss–Seidel: 8 sweeps x 12 steps ----
        // Invariant at loop head: p = h[ii] + sum_{jj!=ii} G[ii][jj]*A[jj]
        // with correct GS recency.
        float4 p;
        {
            const float4* gr = (const float4*)&Gs2[0 * BN + NFIX];
            float4 w0 = gr[0], w1 = gr[1], w2 = gr[2];
            const float wv[NACT] = { w0.x, w0.y, w0.z, w0.w,
                                     w1.x, w1.y, w1.z, w1.w,
                                     w2.x, w2.y, w2.z, w2.w };
            p = h[0];
#pragma unroll
            for (int jj = 1; jj < NACT; jj++) p = fma4(A[jj], wv[jj], p);
        }

        for (int t = 0; t < NITER; t++) {
#pragma unroll
            for (int ii = 0; ii < NACT; ii++) {
                // launch this step's reduction first...
                float s = gsum16(dot4(p, p));

                // ...its latency is hidden by building the next step's partial
                // sum. Single accumulator: the build chain (~10 FMA deep) still
                // fits entirely under the shfl+rsqrt shadow, and saves 4 adds.
                const int nx = (ii + 1) % NACT;
                const float4* gr = (const float4*)&Gs2[nx * BN + NFIX];
                float4 w0 = gr[0], w1 = gr[1], w2 = gr[2];
                const float wv[NACT] = { w0.x, w0.y, w0.z, w0.w,
                                         w1.x, w1.y, w1.z, w1.w,
                                         w2.x, w2.y, w2.z, w2.w };
                float4 q = h[nx];
#pragma unroll
                for (int jj = 0; jj < NACT; jj++) {
                    if (jj == nx || jj == ii) continue;
                    q = fma4(A[jj], wv[jj], q);
                }

                float  inv = -rsqrtf(s);      // s = |p|^2 > 0
                float4 An  = mul4(p, inv);
                A[ii] = An;
                p = fma4(An, wv[ii], q);
            }
        }

        // active outputs (paired reductions)
#pragma unroll
        for (int ii = 0; ii < NACT; ii += 2) {
            float c0 = dot4(A[ii], v0);
            float c1 = dot4(A[ii + 1], v0);
            gsum16_2(c0, c1);
            if (gl == 0) {
                outb[NFIX + ii]     = out_angle(c0);
                outb[NFIX + ii + 1] = out_angle(c1);
            }
        }
    } else {
        // ============ GENERIC PATH (any mask) — cold =========================
        // Per-group full Gram into local memory (16 lanes x 2 float4 span M=128)
        float Gc[BN * BN];
#pragma unroll 1
        for (int e = 0; e < BN * BN; e++) {
            int i = e / BN, j = e % BN;
            float part = dot4(S4[i * 32 + gl],      S4[j * 32 + gl]) +
                         dot4(S4[i * 32 + 16 + gl], S4[j * 32 + 16 + gl]);
            Gc[e] = gsum16(part);
        }

        float4 Vl[BN];
        Vl[0] = v0;
        float nv0g = gsum16(dot4(v0, v0));
#pragma unroll 1
        for (int n = 1; n < BN; n++) {
            float4 f  = vrow[n * 16 + gl];
            float  ss = dot4(f, f);
            float  fv = dot4(f, v0);
            gsum16_2(ss, fv);
            float4 r = mul4(f, rsqrtf(fmaxf(ss, 1e-30f)));
            if ((mask >> n) & 1u) {
                float ww = fmaf(-fv * fv, 2.0f - nv0g, ss);
                float iu = rsqrtf(fmaxf(ww, 1e-24f));
                float4 u = mul4(fma4(v0, -fv, f), iu);
                float sz, cz;
                __sincosf(PIF * z[b * BN + n], &sz, &cz);
                Vl[n] = fma4(v0, -cz, mul4(u, sz));
            } else {
                Vl[n] = r;
            }
        }
#pragma unroll 1
        for (int t = 0; t < NITER; t++) {
#pragma unroll 1
            for (int i = 0; i < BN; i++) {
                if ((mask >> i) & 1u) continue;
                float4 acc = make_float4(0.f, 0.f, 0.f, 0.f);
#pragma unroll 1
                for (int n = 0; n < BN; n++)
                    acc = fma4(Vl[n], Gc[i * BN + n], acc);
                acc = fma4(Vl[i], -Gc[i * BN + i], acc);
                float s = gsum16(dot4(acc, acc));
                Vl[i] = mul4(acc, -rsqrtf(fmaxf(s, 1e-30f)));
            }
        }
#pragma unroll 1
        for (int n = 0; n < BN; n++) {
            float co = gsum16(dot4(Vl[n], v0));
            if (gl == 0) outb[n] = out_angle(co);
        }
    }
}

// ---------------------------------------------------------------------------
extern "C" void kernel_launch(void* const* d_in, const int* in_sizes, int n_in,
                              void* d_out, int out_size) {
    const float* z    = (const float*)d_in[0];   // (B, 24)
    const float* S    = (const float*)d_in[1];   // (24, 128)
    const float* Vr   = (const float*)d_in[2];   // (B, 24, 64)
    const int*   isin = (const int*)d_in[3];     // (B, 24)
    float*       out  = (float*)d_out;           // (B, 24)

    const int B = in_sizes[0] / BN;
    const int grid = (B + GPB - 1) / GPB;
    mix_kernel<<<grid, BLOCK>>>(z, S, Vr, isin, out, B);
}